// round 13
// baseline (speedup 1.0000x reference)
#include <cuda_runtime.h>
#include <math.h>

#define NQV   65536
#define NVV   1558
#define NUMVV 779
#define NB    16

typedef unsigned long long ull;

__device__ __forceinline__ ull pack2(float lo, float hi) {
    ull r; asm("mov.b64 %0,{%1,%2};" : "=l"(r) : "f"(lo), "f"(hi)); return r;
}
__device__ __forceinline__ float2 unpk(ull v) {
    float2 r; asm("mov.b64 {%0,%1},%2;" : "=f"(r.x), "=f"(r.y) : "l"(v)); return r;
}
__device__ __forceinline__ ull ffma2(ull a, ull b, ull c) {
    ull d; asm("fma.rn.f32x2 %0,%1,%2,%3;" : "=l"(d) : "l"(a), "l"(b), "l"(c)); return d;
}
__device__ __forceinline__ ull fadd2(ull a, ull b) {
    ull d; asm("add.rn.f32x2 %0,%1,%2;" : "=l"(d) : "l"(a), "l"(b)); return d;
}
__device__ __forceinline__ ull fmul2(ull a, ull b) {
    ull d; asm("mul.rn.f32x2 %0,%1,%2;" : "=l"(d) : "l"(a), "l"(b)); return d;
}

// scratch
__device__ float  g_A21[21*256*256];
__device__ float  g_A42[42*256*256];
__device__ float  g_B21[21*64*64];
__device__ float  g_B42[42*64*64];
__device__ float2 g_partA[42*NB];
__device__ float2 g_partB[42*NB];
__device__ float  g_gf[42*18];
__device__ float  g_H779[NUMVV*18];
__device__ float  g_vf[NVV*29];
__device__ int    g_idx[NQV];

// ---------------- 2-level channel stats: partial sums ----------------
__global__ void stats_partial(const float* __restrict__ x, int N, float2* __restrict__ part)
{
    __shared__ float s1[256], s2[256];
    int c = blockIdx.x, b = blockIdx.y;
    int cnt = N / 4 / NB;
    const float4* p = (const float4*)(x + (size_t)c * N) + (size_t)b * cnt;
    float a = 0.f, q = 0.f;
    for (int i = threadIdx.x; i < cnt; i += 256) {
        float4 v = p[i];
        a += v.x + v.y + v.z + v.w;
        q += v.x*v.x + v.y*v.y + v.z*v.z + v.w*v.w;
    }
    s1[threadIdx.x] = a; s2[threadIdx.x] = q;
    __syncthreads();
    for (int s = 128; s > 0; s >>= 1) {
        if (threadIdx.x < s) { s1[threadIdx.x] += s1[threadIdx.x+s]; s2[threadIdx.x] += s2[threadIdx.x+s]; }
        __syncthreads();
    }
    if (threadIdx.x == 0) part[c * NB + b] = make_float2(s1[0], s2[0]);
}

__device__ __forceinline__ float2 fold_stats(const float2* __restrict__ part, int c, float invN)
{
    float a = 0.f, q = 0.f;
#pragma unroll
    for (int i = 0; i < NB; i++) { float2 p = part[c * NB + i]; a += p.x; q += p.y; }
    float m = a * invN;
    return make_float2(m, rsqrtf(q * invN - m * m + 1e-6f));
}

// ---------------- 3x3 conv pad1, f32x2 channel pairs, optional fused LN+relu on input ----------------
template<int CIN, int COUT, int HW, bool FLN>
__global__ __launch_bounds__(128) void conv3x3(const float* __restrict__ in,
                                               const float* __restrict__ w,
                                               float* __restrict__ out,
                                               const float2* __restrict__ part,
                                               const float* __restrict__ lng,
                                               const float* __restrict__ lnb)
{
    constexpr int NP  = (COUT + 1) / 2;
    constexpr int NPP = NP + (NP & 1);
    extern __shared__ float sm[];
    float* sin_ = sm;                         // CIN*10*18 halo tile
    ull*   swt  = (ull*)(sm + CIN * 180);     // [CIN*9][NPP] packed channel pairs
    __shared__ float sMean[32], sRstd[32];
    int tid = threadIdx.x;
    int bx = blockIdx.x * 16, by = blockIdx.y * 8;

    if (FLN && tid < CIN) {
        float2 mr = fold_stats(part, tid, 1.f / (float)(HW * HW));
        sMean[tid] = mr.x; sRstd[tid] = mr.y;
    }
    if (FLN) __syncthreads();

    for (int i = tid; i < CIN * 180; i += 128) {
        int ci = i / 180, r = (i % 180) / 18, c = i % 18;
        int gy = by + r - 1, gx = bx + c - 1;
        float v = 0.f;
        if (gy >= 0 && gy < HW && gx >= 0 && gx < HW) {
            v = in[ci * HW * HW + gy * HW + gx];
            if (FLN) {
                int pix = gy * HW + gx;
                v = fmaxf((v - sMean[ci]) * sRstd[ci] * lng[pix] + lnb[pix], 0.f);
            }
        }
        sin_[i] = v;
    }
    for (int i = tid; i < CIN * 9 * NPP; i += 128) {
        int kk = i / NPP, p = i % NPP;
        float lo = (2*p   < COUT) ? w[(2*p)   * CIN * 9 + kk] : 0.f;
        float hi = (2*p+1 < COUT) ? w[(2*p+1) * CIN * 9 + kk] : 0.f;
        swt[i] = pack2(lo, hi);
    }
    __syncthreads();

    int px = tid & 15, py = tid >> 4;
    ull acc[NPP];
#pragma unroll
    for (int p = 0; p < NPP; p++) acc[p] = 0ull;

    for (int ci = 0; ci < CIN; ci++) {
#pragma unroll
        for (int ky = 0; ky < 3; ky++)
#pragma unroll
        for (int kx = 0; kx < 3; kx++) {
            float v = sin_[ci * 180 + (py + ky) * 18 + px + kx];
            ull vd = pack2(v, v);
            const ull* wr = swt + (ci * 9 + ky * 3 + kx) * NPP;
#pragma unroll
            for (int p = 0; p < NPP; p += 2) {
                ulonglong2 wp = *(const ulonglong2*)(wr + p);
                acc[p]   = ffma2(vd, wp.x, acc[p]);
                acc[p+1] = ffma2(vd, wp.y, acc[p+1]);
            }
        }
    }
    int ox = bx + px, oy = by + py;
#pragma unroll
    for (int p = 0; p < NP; p++) {
        float2 r = unpk(acc[p]);
        out[(2*p) * HW * HW + oy * HW + ox] = r.x;
        if (2*p+1 < COUT) out[(2*p+1) * HW * HW + oy * HW + ox] = r.y;
    }
}

// ---------------- adaptive avg pool -> 3x3 with fused LN+relu (stats folded) ----------------
__global__ void apool(const float* __restrict__ A, int HW,
                      const float2* __restrict__ part,
                      const float* __restrict__ lng,  const float* __restrict__ lnb,
                      float* __restrict__ gf, int colbase)
{
    __shared__ float sred[256];
    __shared__ float sM, sR;
    int r = blockIdx.x, c = blockIdx.y;
    if (threadIdx.x == 0) {
        float2 mr = fold_stats(part, c, 1.f / (float)(HW * HW));
        sM = mr.x; sR = mr.y;
    }
    __syncthreads();
    int ri = r / 3, rj = r % 3;
    int ylo = ri * HW / 3, yhi = ((ri + 1) * HW + 2) / 3;
    int xlo = rj * HW / 3, xhi = ((rj + 1) * HW + 2) / 3;
    int wl = xhi - xlo, cnt = (yhi - ylo) * wl;
    const float* base = A + (size_t)c * HW * HW;
    float m = sM, rs = sR;
    float s = 0.f;
    for (int i = threadIdx.x; i < cnt; i += 256) {
        int y = ylo + i / wl, x = xlo + i % wl;
        int pix = y * HW + x;
        s += fmaxf((base[pix] - m) * rs * lng[pix] + lnb[pix], 0.f);
    }
    sred[threadIdx.x] = s;
    __syncthreads();
    for (int st = 128; st > 0; st >>= 1) {
        if (threadIdx.x < st) sred[threadIdx.x] += sred[threadIdx.x + st];
        __syncthreads();
    }
    if (threadIdx.x == 0) gf[c * 18 + colbase + r] = sred[0] / (float)cnt;
}

__device__ __forceinline__ float wsum(float v)
{
#pragma unroll
    for (int o = 16; o > 0; o >>= 1) v += __shfl_xor_sync(0xffffffffu, v, o);
    return v;
}

// ---------------- gt1: conv1d3 42->779 len18, LN(18)+relu ----------------
__global__ void gt1_k(const float* __restrict__ gf, const float* __restrict__ w,
                      const float* __restrict__ g, const float* __restrict__ b,
                      float* __restrict__ out)
{
    __shared__ float s[42 * 18];
    int o = blockIdx.x, t = threadIdx.x;
    for (int i = t; i < 42 * 18; i += 32) s[i] = gf[i];
    __syncthreads();
    float acc = 0.f;
    if (t < 18) {
        const float* wo = w + o * 126;
        for (int c = 0; c < 42; c++) {
#pragma unroll
            for (int k = 0; k < 3; k++) {
                int tt = t + k - 1;
                if (tt >= 0 && tt < 18) acc = fmaf(s[c * 18 + tt], wo[c * 3 + k], acc);
            }
        }
    }
    float v  = (t < 18) ? acc : 0.f;
    float m  = wsum(v) / 18.f;
    float sq = wsum(v * v) / 18.f;
    float rs = rsqrtf(sq - m * m + 1e-6f);
    if (t < 18) out[o * 18 + t] = fmaxf((acc - m) * rs * g[t] + b[t], 0.f);
}

// ---------------- gt2: conv1d3 779->1558 len18, LN(18)+relu -> vf[:,11:29] ----------------
#define GT2_OPB 16
#define GT2_SMEM ((779*19 + GT2_OPB*2337) * 4)
__global__ __launch_bounds__(256) void gt2_k(const float* __restrict__ h,
                                             const float* __restrict__ w,
                                             const float* __restrict__ g,
                                             const float* __restrict__ b,
                                             float* __restrict__ vf)
{
    extern __shared__ float sm[];
    float* Hs = sm;               // 779 x 19 (padded)
    float* Ws = sm + 779 * 19;    // GT2_OPB x 2337
    int ob  = blockIdx.x * GT2_OPB;
    int tid = threadIdx.x;
    int nout = NVV - ob; if (nout > GT2_OPB) nout = GT2_OPB;

    for (int i = tid; i < 779 * 18; i += 256) Hs[(i / 18) * 19 + (i % 18)] = h[i];
    for (int i = tid; i < nout * 2337; i += 256) Ws[i] = w[(size_t)ob * 2337 + i];
    __syncthreads();

    int wid = tid >> 5, lane = tid & 31;
#pragma unroll
    for (int rep = 0; rep < 2; rep++) {
        int oo = wid + rep * 8;
        if (oo >= nout) continue;
        int o = ob + oo;
        float acc[18];
#pragma unroll
        for (int t = 0; t < 18; t++) acc[t] = 0.f;
        for (int c = lane; c < 779; c += 32) {
            const float* wc = Ws + oo * 2337 + c * 3;
            float w0 = wc[0], w1 = wc[1], w2 = wc[2];
            const float* hc = Hs + c * 19;
            float hv[20];
            hv[0] = 0.f; hv[19] = 0.f;
#pragma unroll
            for (int t = 0; t < 18; t++) hv[t + 1] = hc[t];
#pragma unroll
            for (int t = 0; t < 18; t++)
                acc[t] += w0 * hv[t] + w1 * hv[t + 1] + w2 * hv[t + 2];
        }
#pragma unroll
        for (int t = 0; t < 18; t++) acc[t] = wsum(acc[t]);
        float m = 0.f, sq = 0.f;
#pragma unroll
        for (int t = 0; t < 18; t++) { m += acc[t]; sq += acc[t] * acc[t]; }
        m *= (1.f / 18.f); sq *= (1.f / 18.f);
        float rs = rsqrtf(sq - m * m + 1e-6f);
        if (lane < 18)
            vf[o * 29 + 11 + lane] = fmaxf((acc[lane] - m) * rs * g[lane] + b[lane], 0.f);
    }
}

// ---------------- bilinear vertex sampling -> vf[:,0:11] ----------------
__device__ __forceinline__ void bsetup(float c, int L, int& i0, int& i1, float& w)
{
    float xs = (c + 1.f) * 0.5f * (float)(L - 1);
    float f = floorf(xs);
    w = xs - f;
    int a = (int)f;
    i0 = min(max(a, 0), L - 1);
    i1 = min(max(a + 1, 0), L - 1);
}

__global__ void feat_vert_k(const float* __restrict__ vxy, const float* __restrict__ img,
                            const float* __restrict__ ft, float* __restrict__ vf)
{
    int p = blockIdx.x * 256 + threadIdx.x;
    if (p >= NVV) return;
    float xc = vxy[p * 2], yc = vxy[p * 2 + 1];
    int x0, x1, y0, y1; float wx, wy;
    bsetup(xc, 256, x0, x1, wx); bsetup(yc, 256, y0, y1, wy);
#pragma unroll
    for (int c = 0; c < 3; c++) {
        const float* f = img + c * 65536;
        float v00=f[y0*256+x0], v01=f[y0*256+x1], v10=f[y1*256+x0], v11=f[y1*256+x1];
        vf[p*29+c] = v00*(1.f-wx)*(1.f-wy) + v01*wx*(1.f-wy) + v10*(1.f-wx)*wy + v11*wx*wy;
    }
    bsetup(xc, 64, x0, x1, wx); bsetup(yc, 64, y0, y1, wy);
#pragma unroll
    for (int c = 0; c < 8; c++) {
        const float* f = ft + c * 4096;
        float v00=f[y0*64+x0], v01=f[y0*64+x1], v10=f[y1*64+x0], v11=f[y1*64+x1];
        vf[p*29+3+c] = v00*(1.f-wx)*(1.f-wy) + v01*wx*(1.f-wy) + v10*(1.f-wx)*wy + v11*wx*wy;
    }
}

// ---------------- nearest-vertex argmin: 4 queries/thread, f32x2 pairs ----------------
#define AQ 4
__global__ __launch_bounds__(256) void argmin_k(const float* __restrict__ v,
                                                const float* __restrict__ vert,
                                                int* __restrict__ idx)
{
    __shared__ __align__(16) float sx[NVV];
    __shared__ __align__(16) float sy[NVV];
    __shared__ __align__(16) float sz[NVV];
    __shared__ __align__(16) float s2[NVV];
    int tid = threadIdx.x;
    for (int i = tid; i < NVV; i += 256) {
        float x = vert[i*3], y = vert[i*3+1], z = vert[i*3+2];
        sx[i] = x; sy[i] = y; sz[i] = z; s2[i] = x*x + y*y + z*z;
    }
    __syncthreads();

    int qb = blockIdx.x * 256 * AQ + tid;
    ull qx2[AQ], qy2[AQ], qz2[AQ];
    float best[AQ];
    int bi[AQ];
#pragma unroll
    for (int k = 0; k < AQ; k++) {
        int q = qb + k * 256;
        float qx = v[q*3], qy = v[q*3+1], qz = v[q*3+2];
        qx2[k] = pack2(qx, qx); qy2[k] = pack2(qy, qy); qz2[k] = pack2(qz, qz);
        best[k] = 3.4e38f; bi[k] = 0;
    }
    ull m2 = pack2(-2.f, -2.f);
    for (int p = 0; p < NVV; p += 2) {
        ull x2  = *(const ull*)(sx + p);
        ull y2  = *(const ull*)(sy + p);
        ull z2  = *(const ull*)(sz + p);
        ull s22 = *(const ull*)(s2 + p);
#pragma unroll
        for (int k = 0; k < AQ; k++) {
            ull dot = ffma2(x2, qx2[k], ffma2(y2, qy2[k], fmul2(z2, qz2[k])));
            ull d2  = ffma2(dot, m2, s22);
            float2 dd = unpk(d2);
            if (dd.x < best[k]) { best[k] = dd.x; bi[k] = p; }
            if (dd.y < best[k]) { best[k] = dd.y; bi[k] = p + 1; }
        }
    }
#pragma unroll
    for (int k = 0; k < AQ; k++) idx[qb + k * 256] = bi[k];
}

// ---------------- fused per-query MLP stack (persistent CTAs, prefetched gather) ----------------
#define QT 128
#define NTILE (NQV / QT)   // 512
#define FM_GRID 148
#define FM_SMEM 196864

__device__ __forceinline__ void gather24(int qb, int tid,
    const float* __restrict__ img_xy, const float* __restrict__ ft_xy,
    const float* __restrict__ latent, const float* __restrict__ qvis,
    const float* __restrict__ vvis, float* pf)
{
#pragma unroll
    for (int i = 0; i < 24; i++) {
        int e = tid + i * 512;
        int q = e / 96, c = e % 96, gq = qb + q;
        float val;
        if (c < 3) val = img_xy[gq * 3 + c];
        else if (c < 11) val = ft_xy[gq * 8 + (c - 3)];
        else if (c < 69) {
            int i0 = g_idx[gq];
            int i1 = i0 + NUMVV; if (i1 >= NVV) i1 -= NVV;
            if (c < 22)      val = g_vf[i0 * 29 + (c - 11)]      * vvis[i0];
            else if (c < 33) val = g_vf[i1 * 29 + (c - 22)]      * vvis[i1];
            else if (c < 51) val = g_vf[i0 * 29 + 11 + (c - 33)] * vvis[i0];
            else             val = g_vf[i1 * 29 + 11 + (c - 51)] * vvis[i1];
        }
        else if (c < 93) val = latent[gq * 24 + (c - 69)];
        else if (c == 93) val = qvis[gq];
        else {
            int i0 = g_idx[gq];
            if (c == 94) val = vvis[i0];
            else { int i1 = i0 + NUMVV; if (i1 >= NVV) i1 -= NVV; val = vvis[i1]; }
        }
        pf[i] = val;
    }
}

__device__ __forceinline__ void gemm_relu2(const float* __restrict__ A,
                                           const ull* __restrict__ WT,
                                           float* __restrict__ C, int tid)
{
    int q0 = (tid >> 4) << 2;
    int t16 = tid & 15;
    ull acc[4][3];
#pragma unroll
    for (int i = 0; i < 4; i++)
#pragma unroll
        for (int j = 0; j < 3; j++) acc[i][j] = 0ull;
#pragma unroll 2
    for (int ks = 0; ks < 96; ks += 4) {
        float4 a4[4];
#pragma unroll
        for (int i = 0; i < 4; i++) a4[i] = *(const float4*)(A + (q0 + i) * 100 + ks);
        ull w[4][3];
#pragma unroll
        for (int k = 0; k < 4; k++)
#pragma unroll
            for (int j = 0; j < 3; j++)
                w[k][j] = WT[(ks + k) * 48 + t16 + 16 * j];
#pragma unroll
        for (int i = 0; i < 4; i++) {
            ull ak[4];
            ak[0] = pack2(a4[i].x, a4[i].x); ak[1] = pack2(a4[i].y, a4[i].y);
            ak[2] = pack2(a4[i].z, a4[i].z); ak[3] = pack2(a4[i].w, a4[i].w);
#pragma unroll
            for (int k = 0; k < 4; k++)
#pragma unroll
                for (int j = 0; j < 3; j++)
                    acc[i][j] = ffma2(ak[k], w[k][j], acc[i][j]);
        }
    }
#pragma unroll
    for (int i = 0; i < 4; i++)
#pragma unroll
        for (int j = 0; j < 3; j++) {
            float2 r = unpk(acc[i][j]);
            float2 o;
            o.x = fmaxf(r.x, 0.f);
            o.y = fmaxf(r.y, 0.f);
            *(float2*)(C + (q0 + i) * 100 + 2 * (t16 + 16 * j)) = o;
        }
}

__global__ __launch_bounds__(512) void fused_main(
    const float* __restrict__ img_xy, const float* __restrict__ ft_xy,
    const float* __restrict__ latent, const float* __restrict__ qvis,
    const float* __restrict__ vvis,
    const float* __restrict__ at_w1, const float* __restrict__ at_w2,
    const float* __restrict__ fw1, const float* __restrict__ fw2,
    float* __restrict__ out)
{
    extern __shared__ char smc[];
    ull*   uW1 = (ull*)smc;                 // [96][48] k-major pairs of at_w1
    ull*   uF1 = uW1 + 4608;                // [96][48] k-major pairs of fconv_w1
    ull*   uW2 = uF1 + 4608;                // [96][3]  k-major o-pairs of at_w2
    ull*   uF2 = uW2 + 288;                 // [96][20] k-major o-pairs of fconv_w2
    float* Ys  = (float*)(uF2 + 1920);      // 128 x 100
    float* Hs  = Ys + 12800;                // 128 x 100
    float* ATs = Hs + 12800;                // 128 x 6
    int tid = threadIdx.x;

    for (int i = tid; i < 48 * 96; i += 512) {
        int k = i / 48, p = i % 48;
        uW1[i] = pack2(at_w1[(2*p) * 96 + k], at_w1[(2*p+1) * 96 + k]);
        uF1[i] = pack2(fw1[(2*p) * 96 + k],   fw1[(2*p+1) * 96 + k]);
    }
    for (int i = tid; i < 3 * 96; i += 512) {
        int p = i / 96, k = i % 96;
        uW2[k * 3 + p] = pack2(at_w2[(2*p) * 96 + k], at_w2[(2*p+1) * 96 + k]);
    }
    for (int i = tid; i < 20 * 96; i += 512) {
        int p = i / 96, k = i % 96;
        uF2[k * 20 + p] = pack2(fw2[(2*p) * 96 + k], fw2[(2*p+1) * 96 + k]);
    }

    float pf[24];
    int t0 = blockIdx.x;
    if (t0 < NTILE) gather24(t0 * QT, tid, img_xy, ft_xy, latent, qvis, vvis, pf);

    for (int t = t0; t < NTILE; t += FM_GRID) {
        int qb = t * QT;
#pragma unroll
        for (int i = 0; i < 24; i++) {
            int e = tid + i * 512;
            Ys[(e / 96) * 100 + (e % 96)] = pf[i];
        }
        __syncthreads();

        int tn = t + FM_GRID;
        if (tn < NTILE) gather24(tn * QT, tid, img_xy, ft_xy, latent, qvis, vvis, pf);

        gemm_relu2(Ys, uW1, Hs, tid);           // h1 = relu(at_w1 @ y)
        __syncthreads();

        for (int e = tid; e < QT * 3; e += 512) {   // at = sigmoid(at_w2 @ h1)
            int q = e / 3, p = e % 3;
            ull acc0 = 0ull, acc1 = 0ull;
#pragma unroll 6
            for (int k = 0; k < 96; k += 4) {
                float4 h = *(const float4*)(Hs + q * 100 + k);
                acc0 = ffma2(pack2(h.x, h.x), uW2[(k  ) * 3 + p], acc0);
                acc1 = ffma2(pack2(h.y, h.y), uW2[(k+1) * 3 + p], acc1);
                acc0 = ffma2(pack2(h.z, h.z), uW2[(k+2) * 3 + p], acc0);
                acc1 = ffma2(pack2(h.w, h.w), uW2[(k+3) * 3 + p], acc1);
            }
            float2 r = unpk(fadd2(acc0, acc1));
            ATs[q * 6 + 2*p]     = 1.f / (1.f + expf(-r.x));
            ATs[q * 6 + 2*p + 1] = 1.f / (1.f + expf(-r.y));
        }
        __syncthreads();

        for (int e = tid; e < QT * 96; e += 512) {  // y2: scale sections
            int q = e / 96, c = e % 96;
            int s = (c < 11) ? 0 : (c < 22) ? 1 : (c < 33) ? 2 : (c < 51) ? 3 : (c < 69) ? 4 : (c < 93) ? 5 : -1;
            if (s >= 0) Ys[q * 100 + c] *= ATs[q * 6 + s];
        }
        __syncthreads();

        gemm_relu2(Ys, uF1, Hs, tid);           // h2 = relu(fconv_w1 @ y2)
        __syncthreads();

        if (tid < 256) {                        // out = fconv_w2 @ h2
            int q = tid >> 1, pg = tid & 1;
            const ull* wb = uF2 + pg * 10;
            const float* hq = Hs + q * 100;
            ull acc[10];
#pragma unroll
            for (int j = 0; j < 10; j++) acc[j] = 0ull;
#pragma unroll 4
            for (int k = 0; k < 96; k += 2) {
                float2 a = *(const float2*)(hq + k);
                ull ax = pack2(a.x, a.x), ay = pack2(a.y, a.y);
                const ulonglong2* w0 = (const ulonglong2*)(wb + (k    ) * 20);
                const ulonglong2* w1 = (const ulonglong2*)(wb + (k + 1) * 20);
#pragma unroll
                for (int j = 0; j < 5; j++) {
                    ulonglong2 wa = w0[j], wc = w1[j];
                    acc[2*j]   = ffma2(ax, wa.x, acc[2*j]);
                    acc[2*j]   = ffma2(ay, wc.x, acc[2*j]);
                    acc[2*j+1] = ffma2(ax, wa.y, acc[2*j+1]);
                    acc[2*j+1] = ffma2(ay, wc.y, acc[2*j+1]);
                }
            }
            float* ob = out + (size_t)(qb + q) * 40 + pg * 20;
#pragma unroll
            for (int j = 0; j < 5; j++) {
                float2 r0 = unpk(acc[2*j]), r1 = unpk(acc[2*j+1]);
                float4 o4 = make_float4(r0.x, r0.y, r1.x, r1.y);
                *(float4*)(ob + 4*j) = o4;
            }
        }
        __syncthreads();
    }
}

extern "C" void kernel_launch(void* const* d_in, const int* in_sizes, int n_in,
                              void* d_out, int out_size)
{
    const float* vert_xy = (const float*)d_in[0];
    const float* ft1     = (const float*)d_in[1];
    const float* ft_xy   = (const float*)d_in[2];
    const float* vert    = (const float*)d_in[3];
    const float* v       = (const float*)d_in[4];
    const float* vvis    = (const float*)d_in[5];
    const float* qvis    = (const float*)d_in[6];
    const float* img_xy  = (const float*)d_in[7];
    const float* img     = (const float*)d_in[8];
    const float* latent  = (const float*)d_in[9];
    const float* fw1     = (const float*)d_in[10];
    const float* fw2     = (const float*)d_in[11];
    const float* at_w1   = (const float*)d_in[12];
    const float* at_w2   = (const float*)d_in[13];
    const float* gt_w1   = (const float*)d_in[14];
    const float* gt_g1   = (const float*)d_in[15];
    const float* gt_b1   = (const float*)d_in[16];
    const float* gt_w2   = (const float*)d_in[17];
    const float* gt_g2   = (const float*)d_in[18];
    const float* gt_b2   = (const float*)d_in[19];
    const float* c3_w1   = (const float*)d_in[20];
    const float* c3_g1   = (const float*)d_in[21];
    const float* c3_b1   = (const float*)d_in[22];
    const float* c3_w2   = (const float*)d_in[23];
    const float* c3_g2   = (const float*)d_in[24];
    const float* c3_b2   = (const float*)d_in[25];
    const float* c4_w1   = (const float*)d_in[26];
    const float* c4_g1   = (const float*)d_in[27];
    const float* c4_b1   = (const float*)d_in[28];
    const float* c4_w2   = (const float*)d_in[29];
    const float* c4_g2   = (const float*)d_in[30];
    const float* c4_b2   = (const float*)d_in[31];
    float* out = (float*)d_out;

    float *A21, *A42, *B21, *B42, *gf, *H779, *vf;
    float2 *partA, *partB;
    int* idx;
    cudaGetSymbolAddress((void**)&A21,   g_A21);
    cudaGetSymbolAddress((void**)&A42,   g_A42);
    cudaGetSymbolAddress((void**)&B21,   g_B21);
    cudaGetSymbolAddress((void**)&B42,   g_B42);
    cudaGetSymbolAddress((void**)&partA, g_partA);
    cudaGetSymbolAddress((void**)&partB, g_partB);
    cudaGetSymbolAddress((void**)&gf,    g_gf);
    cudaGetSymbolAddress((void**)&H779,  g_H779);
    cudaGetSymbolAddress((void**)&vf,    g_vf);
    cudaGetSymbolAddress((void**)&idx,   g_idx);

    static bool init_done = false;
    static cudaStream_t s2, s3;
    static cudaEvent_t evFork, evJ2, evJ3;
    if (!init_done) {
        cudaStreamCreateWithFlags(&s2, cudaStreamNonBlocking);
        cudaStreamCreateWithFlags(&s3, cudaStreamNonBlocking);
        cudaEventCreateWithFlags(&evFork, cudaEventDisableTiming);
        cudaEventCreateWithFlags(&evJ2, cudaEventDisableTiming);
        cudaEventCreateWithFlags(&evJ3, cudaEventDisableTiming);
        cudaFuncSetAttribute(gt2_k, cudaFuncAttributeMaxDynamicSharedMemorySize, GT2_SMEM);
        cudaFuncSetAttribute(fused_main, cudaFuncAttributeMaxDynamicSharedMemorySize, FM_SMEM);
        init_done = true;
    }

    cudaEventRecord(evFork, 0);
    cudaStreamWaitEvent(s2, evFork, 0);
    cudaStreamWaitEvent(s3, evFork, 0);

    // s2: nearest vertex (independent, 4 queries/thread)
    argmin_k<<<NQV / (256 * AQ), 256, 0, s2>>>(v, vert, idx);
    cudaEventRecord(evJ2, s2);

    // s3: vertex sampling + c3 branch (ft1 64x64)
    feat_vert_k<<<(NVV + 255) / 256, 256, 0, s3>>>(vert_xy, img, ft1, vf);
    conv3x3<8, 21, 64, false><<<dim3(4, 8), 128, 8*180*4 + 8*9*12*8, s3>>>(
        ft1, c3_w1, B21, nullptr, nullptr, nullptr);
    stats_partial<<<dim3(21, NB), 256, 0, s3>>>(B21, 4096, partB);
    conv3x3<21, 42, 64, true><<<dim3(4, 8), 128, 21*180*4 + 21*9*22*8, s3>>>(
        B21, c3_w2, B42, partB, c3_g1, c3_b1);
    stats_partial<<<dim3(42, NB), 256, 0, s3>>>(B42, 4096, partB);
    apool<<<dim3(9, 42), 256, 0, s3>>>(B42, 64, partB, c3_g2, c3_b2, gf, 9);
    cudaEventRecord(evJ3, s3);

    // main: c4 branch (img_fmap 256x256)
    conv3x3<3, 21, 256, false><<<dim3(16, 32), 128, 3*180*4 + 3*9*12*8>>>(
        img, c4_w1, A21, nullptr, nullptr, nullptr);
    stats_partial<<<dim3(21, NB), 256>>>(A21, 65536, partA);
    conv3x3<21, 42, 256, true><<<dim3(16, 32), 128, 21*180*4 + 21*9*22*8>>>(
        A21, c4_w2, A42, partA, c4_g1, c4_b1);
    stats_partial<<<dim3(42, NB), 256>>>(A42, 65536, partA);
    apool<<<dim3(9, 42), 256>>>(A42, 256, partA, c4_g2, c4_b2, gf, 0);

    // join c3 branch, then graph convs
    cudaStreamWaitEvent(0, evJ3, 0);
    gt1_k<<<NUMVV, 32>>>(gf, gt_w1, gt_g1, gt_b1, H779);
    gt2_k<<<(NVV + GT2_OPB - 1) / GT2_OPB, 256, GT2_SMEM>>>(H779, gt_w2, gt_g2, gt_b2, vf);

    // join argmin, then fused MLP (persistent, prefetched gather)
    cudaStreamWaitEvent(0, evJ2, 0);
    fused_main<<<FM_GRID, 512, FM_SMEM>>>(img_xy, ft_xy, latent, qvis, vvis,
                                          at_w1, at_w2, fw1, fw2, out);
}

// round 14
// speedup vs baseline: 1.0864x; 1.0864x over previous
#include <cuda_runtime.h>
#include <math.h>

#define NQV   65536
#define NVV   1558
#define NUMVV 779
#define NB    32

typedef unsigned long long ull;

__device__ __forceinline__ ull pack2(float lo, float hi) {
    ull r; asm("mov.b64 %0,{%1,%2};" : "=l"(r) : "f"(lo), "f"(hi)); return r;
}
__device__ __forceinline__ float2 unpk(ull v) {
    float2 r; asm("mov.b64 {%0,%1},%2;" : "=f"(r.x), "=f"(r.y) : "l"(v)); return r;
}
__device__ __forceinline__ ull ffma2(ull a, ull b, ull c) {
    ull d; asm("fma.rn.f32x2 %0,%1,%2,%3;" : "=l"(d) : "l"(a), "l"(b), "l"(c)); return d;
}
__device__ __forceinline__ ull fadd2(ull a, ull b) {
    ull d; asm("add.rn.f32x2 %0,%1,%2;" : "=l"(d) : "l"(a), "l"(b)); return d;
}
__device__ __forceinline__ ull fmul2(ull a, ull b) {
    ull d; asm("mul.rn.f32x2 %0,%1,%2;" : "=l"(d) : "l"(a), "l"(b)); return d;
}

// scratch
__device__ float  g_A21[21*256*256];
__device__ float  g_A42[42*256*256];
__device__ float  g_B21[21*64*64];
__device__ float  g_B42[42*64*64];
__device__ float2 g_partA[42*NB];
__device__ float2 g_partB[42*NB];
__device__ float  g_gf[42*18];
__device__ float  g_H779[NUMVV*18];
__device__ float  g_vf[NVV*29];
__device__ int    g_idx[NQV];

// ---------------- 2-level channel stats: partial sums ----------------
__global__ void stats_partial(const float* __restrict__ x, int N, float2* __restrict__ part)
{
    __shared__ float s1[256], s2[256];
    int c = blockIdx.x, b = blockIdx.y;
    int cnt = N / 4 / NB;
    const float4* p = (const float4*)(x + (size_t)c * N) + (size_t)b * cnt;
    float a = 0.f, q = 0.f;
    for (int i = threadIdx.x; i < cnt; i += 256) {
        float4 v = p[i];
        a += v.x + v.y + v.z + v.w;
        q += v.x*v.x + v.y*v.y + v.z*v.z + v.w*v.w;
    }
    s1[threadIdx.x] = a; s2[threadIdx.x] = q;
    __syncthreads();
    for (int s = 128; s > 0; s >>= 1) {
        if (threadIdx.x < s) { s1[threadIdx.x] += s1[threadIdx.x+s]; s2[threadIdx.x] += s2[threadIdx.x+s]; }
        __syncthreads();
    }
    if (threadIdx.x == 0) part[c * NB + b] = make_float2(s1[0], s2[0]);
}

__device__ __forceinline__ float2 fold_stats(const float2* __restrict__ part, int c, float invN)
{
    float a = 0.f, q = 0.f;
#pragma unroll
    for (int i = 0; i < NB; i++) { float2 p = part[c * NB + i]; a += p.x; q += p.y; }
    float m = a * invN;
    return make_float2(m, rsqrtf(q * invN - m * m + 1e-6f));
}

// ---------------- 3x3 conv pad1, f32x2 channel pairs, optional fused LN+relu on input ----------------
template<int CIN, int COUT, int HW, bool FLN>
__global__ __launch_bounds__(128) void conv3x3(const float* __restrict__ in,
                                               const float* __restrict__ w,
                                               float* __restrict__ out,
                                               const float2* __restrict__ part,
                                               const float* __restrict__ lng,
                                               const float* __restrict__ lnb)
{
    constexpr int NP  = (COUT + 1) / 2;
    constexpr int NPP = NP + (NP & 1);
    extern __shared__ float sm[];
    float* sin_ = sm;                         // CIN*10*18 halo tile
    ull*   swt  = (ull*)(sm + CIN * 180);     // [CIN*9][NPP] packed channel pairs
    __shared__ float sMean[32], sRstd[32];
    int tid = threadIdx.x;
    int bx = blockIdx.x * 16, by = blockIdx.y * 8;

    if (FLN && tid < CIN) {
        float2 mr = fold_stats(part, tid, 1.f / (float)(HW * HW));
        sMean[tid] = mr.x; sRstd[tid] = mr.y;
    }
    if (FLN) __syncthreads();

    for (int i = tid; i < CIN * 180; i += 128) {
        int ci = i / 180, r = (i % 180) / 18, c = i % 18;
        int gy = by + r - 1, gx = bx + c - 1;
        float v = 0.f;
        if (gy >= 0 && gy < HW && gx >= 0 && gx < HW) {
            v = in[ci * HW * HW + gy * HW + gx];
            if (FLN) {
                int pix = gy * HW + gx;
                v = fmaxf((v - sMean[ci]) * sRstd[ci] * lng[pix] + lnb[pix], 0.f);
            }
        }
        sin_[i] = v;
    }
    for (int i = tid; i < CIN * 9 * NPP; i += 128) {
        int kk = i / NPP, p = i % NPP;
        float lo = (2*p   < COUT) ? w[(2*p)   * CIN * 9 + kk] : 0.f;
        float hi = (2*p+1 < COUT) ? w[(2*p+1) * CIN * 9 + kk] : 0.f;
        swt[i] = pack2(lo, hi);
    }
    __syncthreads();

    int px = tid & 15, py = tid >> 4;
    ull acc[NPP];
#pragma unroll
    for (int p = 0; p < NPP; p++) acc[p] = 0ull;

    for (int ci = 0; ci < CIN; ci++) {
#pragma unroll
        for (int ky = 0; ky < 3; ky++)
#pragma unroll
        for (int kx = 0; kx < 3; kx++) {
            float v = sin_[ci * 180 + (py + ky) * 18 + px + kx];
            ull vd = pack2(v, v);
            const ull* wr = swt + (ci * 9 + ky * 3 + kx) * NPP;
#pragma unroll
            for (int p = 0; p < NPP; p += 2) {
                ulonglong2 wp = *(const ulonglong2*)(wr + p);
                acc[p]   = ffma2(vd, wp.x, acc[p]);
                acc[p+1] = ffma2(vd, wp.y, acc[p+1]);
            }
        }
    }
    int ox = bx + px, oy = by + py;
#pragma unroll
    for (int p = 0; p < NP; p++) {
        float2 r = unpk(acc[p]);
        out[(2*p) * HW * HW + oy * HW + ox] = r.x;
        if (2*p+1 < COUT) out[(2*p+1) * HW * HW + oy * HW + ox] = r.y;
    }
}

// ---------------- adaptive avg pool -> 3x3 with fused LN+relu (stats folded) ----------------
__global__ void apool(const float* __restrict__ A, int HW,
                      const float2* __restrict__ part,
                      const float* __restrict__ lng,  const float* __restrict__ lnb,
                      float* __restrict__ gf, int colbase)
{
    __shared__ float sred[256];
    __shared__ float sM, sR;
    int r = blockIdx.x, c = blockIdx.y;
    if (threadIdx.x == 0) {
        float2 mr = fold_stats(part, c, 1.f / (float)(HW * HW));
        sM = mr.x; sR = mr.y;
    }
    __syncthreads();
    int ri = r / 3, rj = r % 3;
    int ylo = ri * HW / 3, yhi = ((ri + 1) * HW + 2) / 3;
    int xlo = rj * HW / 3, xhi = ((rj + 1) * HW + 2) / 3;
    int wl = xhi - xlo, cnt = (yhi - ylo) * wl;
    const float* base = A + (size_t)c * HW * HW;
    float m = sM, rs = sR;
    float s = 0.f;
    for (int i = threadIdx.x; i < cnt; i += 256) {
        int y = ylo + i / wl, x = xlo + i % wl;
        int pix = y * HW + x;
        s += fmaxf((base[pix] - m) * rs * lng[pix] + lnb[pix], 0.f);
    }
    sred[threadIdx.x] = s;
    __syncthreads();
    for (int st = 128; st > 0; st >>= 1) {
        if (threadIdx.x < st) sred[threadIdx.x] += sred[threadIdx.x + st];
        __syncthreads();
    }
    if (threadIdx.x == 0) gf[c * 18 + colbase + r] = sred[0] / (float)cnt;
}

__device__ __forceinline__ float wsum(float v)
{
#pragma unroll
    for (int o = 16; o > 0; o >>= 1) v += __shfl_xor_sync(0xffffffffu, v, o);
    return v;
}

// ---------------- gt1: conv1d3 42->779 len18, LN(18)+relu ----------------
__global__ void gt1_k(const float* __restrict__ gf, const float* __restrict__ w,
                      const float* __restrict__ g, const float* __restrict__ b,
                      float* __restrict__ out)
{
    __shared__ float s[42 * 18];
    int o = blockIdx.x, t = threadIdx.x;
    for (int i = t; i < 42 * 18; i += 32) s[i] = gf[i];
    __syncthreads();
    float acc = 0.f;
    if (t < 18) {
        const float* wo = w + o * 126;
        for (int c = 0; c < 42; c++) {
#pragma unroll
            for (int k = 0; k < 3; k++) {
                int tt = t + k - 1;
                if (tt >= 0 && tt < 18) acc = fmaf(s[c * 18 + tt], wo[c * 3 + k], acc);
            }
        }
    }
    float v  = (t < 18) ? acc : 0.f;
    float m  = wsum(v) / 18.f;
    float sq = wsum(v * v) / 18.f;
    float rs = rsqrtf(sq - m * m + 1e-6f);
    if (t < 18) out[o * 18 + t] = fmaxf((acc - m) * rs * g[t] + b[t], 0.f);
}

// ---------------- gt2: conv1d3 779->1558 len18, LN(18)+relu -> vf[:,11:29] ----------------
// H rows stored padded as 20 floats: [0, h0..h17, 0] -> aligned ull pairs, f32x2 inner loop.
#define GT2_OPB 16
#define GT2_SMEM ((779*20 + GT2_OPB*2337) * 4)
__global__ __launch_bounds__(256) void gt2_k(const float* __restrict__ h,
                                             const float* __restrict__ w,
                                             const float* __restrict__ g,
                                             const float* __restrict__ b,
                                             float* __restrict__ vf)
{
    extern __shared__ float sm[];
    float* Hs = sm;               // 779 x 20 padded [0, h0..h17, 0]
    float* Ws = sm + 779 * 20;    // GT2_OPB x 2337
    int ob  = blockIdx.x * GT2_OPB;
    int tid = threadIdx.x;
    int nout = NVV - ob; if (nout > GT2_OPB) nout = GT2_OPB;

    for (int i = tid; i < 779 * 18; i += 256) Hs[(i / 18) * 20 + 1 + (i % 18)] = h[i];
    for (int i = tid; i < 779; i += 256) { Hs[i * 20] = 0.f; Hs[i * 20 + 19] = 0.f; }
    for (int i = tid; i < nout * 2337; i += 256) Ws[i] = w[(size_t)ob * 2337 + i];
    __syncthreads();

    int wid = tid >> 5, lane = tid & 31;
#pragma unroll
    for (int rep = 0; rep < 2; rep++) {
        int oo = wid + rep * 8;
        if (oo >= nout) continue;
        int o = ob + oo;
        ull acc[9];
#pragma unroll
        for (int j = 0; j < 9; j++) acc[j] = 0ull;
        for (int c = lane; c < NUMVV; c += 32) {
            const float* wc = Ws + oo * 2337 + c * 3;
            ull w0 = pack2(wc[0], wc[0]);
            ull w1 = pack2(wc[1], wc[1]);
            ull w2 = pack2(wc[2], wc[2]);
            const ull* U = (const ull*)(Hs + c * 20);   // U[j] = (P[2j], P[2j+1]), j=0..9
            ull u[10];
#pragma unroll
            for (int j = 0; j < 10; j++) u[j] = U[j];
#pragma unroll
            for (int j = 0; j < 9; j++) {
                float2 a = unpk(u[j]);
                float2 bb = unpk(u[j + 1]);
                ull mid = pack2(a.y, bb.x);             // (P[2j+1], P[2j+2])
                acc[j] = ffma2(w0, u[j], acc[j]);
                acc[j] = ffma2(w1, mid, acc[j]);
                acc[j] = ffma2(w2, u[j + 1], acc[j]);
            }
        }
        float av[18];
#pragma unroll
        for (int j = 0; j < 9; j++) {
            float2 r = unpk(acc[j]);
            av[2*j] = r.x; av[2*j + 1] = r.y;
        }
#pragma unroll
        for (int t = 0; t < 18; t++) av[t] = wsum(av[t]);
        float m = 0.f, sq = 0.f;
#pragma unroll
        for (int t = 0; t < 18; t++) { m += av[t]; sq += av[t] * av[t]; }
        m *= (1.f / 18.f); sq *= (1.f / 18.f);
        float rs = rsqrtf(sq - m * m + 1e-6f);
        if (lane < 18)
            vf[o * 29 + 11 + lane] = fmaxf((av[lane] - m) * rs * g[lane] + b[lane], 0.f);
    }
}

// ---------------- bilinear vertex sampling -> vf[:,0:11] ----------------
__device__ __forceinline__ void bsetup(float c, int L, int& i0, int& i1, float& w)
{
    float xs = (c + 1.f) * 0.5f * (float)(L - 1);
    float f = floorf(xs);
    w = xs - f;
    int a = (int)f;
    i0 = min(max(a, 0), L - 1);
    i1 = min(max(a + 1, 0), L - 1);
}

__global__ void feat_vert_k(const float* __restrict__ vxy, const float* __restrict__ img,
                            const float* __restrict__ ft, float* __restrict__ vf)
{
    int p = blockIdx.x * 256 + threadIdx.x;
    if (p >= NVV) return;
    float xc = vxy[p * 2], yc = vxy[p * 2 + 1];
    int x0, x1, y0, y1; float wx, wy;
    bsetup(xc, 256, x0, x1, wx); bsetup(yc, 256, y0, y1, wy);
#pragma unroll
    for (int c = 0; c < 3; c++) {
        const float* f = img + c * 65536;
        float v00=f[y0*256+x0], v01=f[y0*256+x1], v10=f[y1*256+x0], v11=f[y1*256+x1];
        vf[p*29+c] = v00*(1.f-wx)*(1.f-wy) + v01*wx*(1.f-wy) + v10*(1.f-wx)*wy + v11*wx*wy;
    }
    bsetup(xc, 64, x0, x1, wx); bsetup(yc, 64, y0, y1, wy);
#pragma unroll
    for (int c = 0; c < 8; c++) {
        const float* f = ft + c * 4096;
        float v00=f[y0*64+x0], v01=f[y0*64+x1], v10=f[y1*64+x0], v11=f[y1*64+x1];
        vf[p*29+3+c] = v00*(1.f-wx)*(1.f-wy) + v01*wx*(1.f-wy) + v10*(1.f-wx)*wy + v11*wx*wy;
    }
}

// ---------------- nearest-vertex argmin, f32x2 pairs (1 query/thread) ----------------
__global__ __launch_bounds__(256) void argmin_k(const float* __restrict__ v,
                                                const float* __restrict__ vert,
                                                int* __restrict__ idx)
{
    __shared__ __align__(16) float sx[NVV];
    __shared__ __align__(16) float sy[NVV];
    __shared__ __align__(16) float sz[NVV];
    __shared__ __align__(16) float s2[NVV];
    int tid = threadIdx.x;
    for (int i = tid; i < NVV; i += 256) {
        float x = vert[i*3], y = vert[i*3+1], z = vert[i*3+2];
        sx[i] = x; sy[i] = y; sz[i] = z; s2[i] = x*x + y*y + z*z;
    }
    __syncthreads();
    int q = blockIdx.x * 256 + tid;
    float qx = v[q*3], qy = v[q*3+1], qz = v[q*3+2];
    ull qx2 = pack2(qx, qx), qy2 = pack2(qy, qy), qz2 = pack2(qz, qz);
    ull m2  = pack2(-2.f, -2.f);
    float best = 3.4e38f; int bi = 0;
    for (int p = 0; p < NVV; p += 2) {
        ull x2 = *(const ull*)(sx + p);
        ull y2 = *(const ull*)(sy + p);
        ull z2 = *(const ull*)(sz + p);
        ull s22 = *(const ull*)(s2 + p);
        ull dot = ffma2(x2, qx2, ffma2(y2, qy2, fmul2(z2, qz2)));
        ull d2  = ffma2(dot, m2, s22);
        float2 dd = unpk(d2);
        if (dd.x < best) { best = dd.x; bi = p; }
        if (dd.y < best) { best = dd.y; bi = p + 1; }
    }
    idx[q] = bi;
}

// ---------------- fused per-query MLP stack (persistent CTAs, prefetched gather) ----------------
#define QT 128
#define NTILE (NQV / QT)   // 512
#define FM_GRID 148
#define FM_SMEM 196864

__device__ __forceinline__ void gather24(int qb, int tid,
    const float* __restrict__ img_xy, const float* __restrict__ ft_xy,
    const float* __restrict__ latent, const float* __restrict__ qvis,
    const float* __restrict__ vvis, float* pf)
{
#pragma unroll
    for (int i = 0; i < 24; i++) {
        int e = tid + i * 512;
        int q = e / 96, c = e % 96, gq = qb + q;
        float val;
        if (c < 3) val = img_xy[gq * 3 + c];
        else if (c < 11) val = ft_xy[gq * 8 + (c - 3)];
        else if (c < 69) {
            int i0 = g_idx[gq];
            int i1 = i0 + NUMVV; if (i1 >= NVV) i1 -= NVV;
            if (c < 22)      val = g_vf[i0 * 29 + (c - 11)]      * vvis[i0];
            else if (c < 33) val = g_vf[i1 * 29 + (c - 22)]      * vvis[i1];
            else if (c < 51) val = g_vf[i0 * 29 + 11 + (c - 33)] * vvis[i0];
            else             val = g_vf[i1 * 29 + 11 + (c - 51)] * vvis[i1];
        }
        else if (c < 93) val = latent[gq * 24 + (c - 69)];
        else if (c == 93) val = qvis[gq];
        else {
            int i0 = g_idx[gq];
            if (c == 94) val = vvis[i0];
            else { int i1 = i0 + NUMVV; if (i1 >= NVV) i1 -= NVV; val = vvis[i1]; }
        }
        pf[i] = val;
    }
}

__device__ __forceinline__ void gemm_relu2(const float* __restrict__ A,
                                           const ull* __restrict__ WT,
                                           float* __restrict__ C, int tid)
{
    int q0 = (tid >> 4) << 2;
    int t16 = tid & 15;
    ull acc[4][3];
#pragma unroll
    for (int i = 0; i < 4; i++)
#pragma unroll
        for (int j = 0; j < 3; j++) acc[i][j] = 0ull;
#pragma unroll 2
    for (int ks = 0; ks < 96; ks += 4) {
        float4 a4[4];
#pragma unroll
        for (int i = 0; i < 4; i++) a4[i] = *(const float4*)(A + (q0 + i) * 100 + ks);
        ull w[4][3];
#pragma unroll
        for (int k = 0; k < 4; k++)
#pragma unroll
            for (int j = 0; j < 3; j++)
                w[k][j] = WT[(ks + k) * 48 + t16 + 16 * j];
#pragma unroll
        for (int i = 0; i < 4; i++) {
            ull ak[4];
            ak[0] = pack2(a4[i].x, a4[i].x); ak[1] = pack2(a4[i].y, a4[i].y);
            ak[2] = pack2(a4[i].z, a4[i].z); ak[3] = pack2(a4[i].w, a4[i].w);
#pragma unroll
            for (int k = 0; k < 4; k++)
#pragma unroll
                for (int j = 0; j < 3; j++)
                    acc[i][j] = ffma2(ak[k], w[k][j], acc[i][j]);
        }
    }
#pragma unroll
    for (int i = 0; i < 4; i++)
#pragma unroll
        for (int j = 0; j < 3; j++) {
            float2 r = unpk(acc[i][j]);
            float2 o;
            o.x = fmaxf(r.x, 0.f);
            o.y = fmaxf(r.y, 0.f);
            *(float2*)(C + (q0 + i) * 100 + 2 * (t16 + 16 * j)) = o;
        }
}

__global__ __launch_bounds__(512) void fused_main(
    const float* __restrict__ img_xy, const float* __restrict__ ft_xy,
    const float* __restrict__ latent, const float* __restrict__ qvis,
    const float* __restrict__ vvis,
    const float* __restrict__ at_w1, const float* __restrict__ at_w2,
    const float* __restrict__ fw1, const float* __restrict__ fw2,
    float* __restrict__ out)
{
    extern __shared__ char smc[];
    ull*   uW1 = (ull*)smc;                 // [96][48] k-major pairs of at_w1
    ull*   uF1 = uW1 + 4608;                // [96][48] k-major pairs of fconv_w1
    ull*   uW2 = uF1 + 4608;                // [96][3]  k-major o-pairs of at_w2
    ull*   uF2 = uW2 + 288;                 // [96][20] k-major o-pairs of fconv_w2
    float* Ys  = (float*)(uF2 + 1920);      // 128 x 100
    float* Hs  = Ys + 12800;                // 128 x 100
    float* ATs = Hs + 12800;                // 128 x 6
    int tid = threadIdx.x;

    for (int i = tid; i < 48 * 96; i += 512) {
        int k = i / 48, p = i % 48;
        uW1[i] = pack2(at_w1[(2*p) * 96 + k], at_w1[(2*p+1) * 96 + k]);
        uF1[i] = pack2(fw1[(2*p) * 96 + k],   fw1[(2*p+1) * 96 + k]);
    }
    for (int i = tid; i < 3 * 96; i += 512) {
        int p = i / 96, k = i % 96;
        uW2[k * 3 + p] = pack2(at_w2[(2*p) * 96 + k], at_w2[(2*p+1) * 96 + k]);
    }
    for (int i = tid; i < 20 * 96; i += 512) {
        int p = i / 96, k = i % 96;
        uF2[k * 20 + p] = pack2(fw2[(2*p) * 96 + k], fw2[(2*p+1) * 96 + k]);
    }

    float pf[24];
    int t0 = blockIdx.x;
    if (t0 < NTILE) gather24(t0 * QT, tid, img_xy, ft_xy, latent, qvis, vvis, pf);

    for (int t = t0; t < NTILE; t += FM_GRID) {
        int qb = t * QT;
#pragma unroll
        for (int i = 0; i < 24; i++) {
            int e = tid + i * 512;
            Ys[(e / 96) * 100 + (e % 96)] = pf[i];
        }
        __syncthreads();

        int tn = t + FM_GRID;
        if (tn < NTILE) gather24(tn * QT, tid, img_xy, ft_xy, latent, qvis, vvis, pf);

        gemm_relu2(Ys, uW1, Hs, tid);           // h1 = relu(at_w1 @ y)
        __syncthreads();

        for (int e = tid; e < QT * 3; e += 512) {   // at = sigmoid(at_w2 @ h1)
            int q = e / 3, p = e % 3;
            ull acc0 = 0ull, acc1 = 0ull;
#pragma unroll 6
            for (int k = 0; k < 96; k += 4) {
                float4 h = *(const float4*)(Hs + q * 100 + k);
                acc0 = ffma2(pack2(h.x, h.x), uW2[(k  ) * 3 + p], acc0);
                acc1 = ffma2(pack2(h.y, h.y), uW2[(k+1) * 3 + p], acc1);
                acc0 = ffma2(pack2(h.z, h.z), uW2[(k+2) * 3 + p], acc0);
                acc1 = ffma2(pack2(h.w, h.w), uW2[(k+3) * 3 + p], acc1);
            }
            float2 r = unpk(fadd2(acc0, acc1));
            ATs[q * 6 + 2*p]     = 1.f / (1.f + expf(-r.x));
            ATs[q * 6 + 2*p + 1] = 1.f / (1.f + expf(-r.y));
        }
        __syncthreads();

        for (int e = tid; e < QT * 96; e += 512) {  // y2: scale sections
            int q = e / 96, c = e % 96;
            int s = (c < 11) ? 0 : (c < 22) ? 1 : (c < 33) ? 2 : (c < 51) ? 3 : (c < 69) ? 4 : (c < 93) ? 5 : -1;
            if (s >= 0) Ys[q * 100 + c] *= ATs[q * 6 + s];
        }
        __syncthreads();

        gemm_relu2(Ys, uF1, Hs, tid);           // h2 = relu(fconv_w1 @ y2)
        __syncthreads();

        if (tid < 256) {                        // out = fconv_w2 @ h2
            int q = tid >> 1, pg = tid & 1;
            const ull* wb = uF2 + pg * 10;
            const float* hq = Hs + q * 100;
            ull acc[10];
#pragma unroll
            for (int j = 0; j < 10; j++) acc[j] = 0ull;
#pragma unroll 4
            for (int k = 0; k < 96; k += 2) {
                float2 a = *(const float2*)(hq + k);
                ull ax = pack2(a.x, a.x), ay = pack2(a.y, a.y);
                const ulonglong2* w0 = (const ulonglong2*)(wb + (k    ) * 20);
                const ulonglong2* w1 = (const ulonglong2*)(wb + (k + 1) * 20);
#pragma unroll
                for (int j = 0; j < 5; j++) {
                    ulonglong2 wa = w0[j], wc = w1[j];
                    acc[2*j]   = ffma2(ax, wa.x, acc[2*j]);
                    acc[2*j]   = ffma2(ay, wc.x, acc[2*j]);
                    acc[2*j+1] = ffma2(ax, wa.y, acc[2*j+1]);
                    acc[2*j+1] = ffma2(ay, wc.y, acc[2*j+1]);
                }
            }
            float* ob = out + (size_t)(qb + q) * 40 + pg * 20;
#pragma unroll
            for (int j = 0; j < 5; j++) {
                float2 r0 = unpk(acc[2*j]), r1 = unpk(acc[2*j+1]);
                float4 o4 = make_float4(r0.x, r0.y, r1.x, r1.y);
                *(float4*)(ob + 4*j) = o4;
            }
        }
        __syncthreads();
    }
}

extern "C" void kernel_launch(void* const* d_in, const int* in_sizes, int n_in,
                              void* d_out, int out_size)
{
    const float* vert_xy = (const float*)d_in[0];
    const float* ft1     = (const float*)d_in[1];
    const float* ft_xy   = (const float*)d_in[2];
    const float* vert    = (const float*)d_in[3];
    const float* v       = (const float*)d_in[4];
    const float* vvis    = (const float*)d_in[5];
    const float* qvis    = (const float*)d_in[6];
    const float* img_xy  = (const float*)d_in[7];
    const float* img     = (const float*)d_in[8];
    const float* latent  = (const float*)d_in[9];
    const float* fw1     = (const float*)d_in[10];
    const float* fw2     = (const float*)d_in[11];
    const float* at_w1   = (const float*)d_in[12];
    const float* at_w2   = (const float*)d_in[13];
    const float* gt_w1   = (const float*)d_in[14];
    const float* gt_g1   = (const float*)d_in[15];
    const float* gt_b1   = (const float*)d_in[16];
    const float* gt_w2   = (const float*)d_in[17];
    const float* gt_g2   = (const float*)d_in[18];
    const float* gt_b2   = (const float*)d_in[19];
    const float* c3_w1   = (const float*)d_in[20];
    const float* c3_g1   = (const float*)d_in[21];
    const float* c3_b1   = (const float*)d_in[22];
    const float* c3_w2   = (const float*)d_in[23];
    const float* c3_g2   = (const float*)d_in[24];
    const float* c3_b2   = (const float*)d_in[25];
    const float* c4_w1   = (const float*)d_in[26];
    const float* c4_g1   = (const float*)d_in[27];
    const float* c4_b1   = (const float*)d_in[28];
    const float* c4_w2   = (const float*)d_in[29];
    const float* c4_g2   = (const float*)d_in[30];
    const float* c4_b2   = (const float*)d_in[31];
    float* out = (float*)d_out;

    float *A21, *A42, *B21, *B42, *gf, *H779, *vf;
    float2 *partA, *partB;
    int* idx;
    cudaGetSymbolAddress((void**)&A21,   g_A21);
    cudaGetSymbolAddress((void**)&A42,   g_A42);
    cudaGetSymbolAddress((void**)&B21,   g_B21);
    cudaGetSymbolAddress((void**)&B42,   g_B42);
    cudaGetSymbolAddress((void**)&partA, g_partA);
    cudaGetSymbolAddress((void**)&partB, g_partB);
    cudaGetSymbolAddress((void**)&gf,    g_gf);
    cudaGetSymbolAddress((void**)&H779,  g_H779);
    cudaGetSymbolAddress((void**)&vf,    g_vf);
    cudaGetSymbolAddress((void**)&idx,   g_idx);

    static bool init_done = false;
    static cudaStream_t s2, s3;
    static cudaEvent_t evFork, evJ2, evJ3;
    if (!init_done) {
        cudaStreamCreateWithFlags(&s2, cudaStreamNonBlocking);
        cudaStreamCreateWithFlags(&s3, cudaStreamNonBlocking);
        cudaEventCreateWithFlags(&evFork, cudaEventDisableTiming);
        cudaEventCreateWithFlags(&evJ2, cudaEventDisableTiming);
        cudaEventCreateWithFlags(&evJ3, cudaEventDisableTiming);
        cudaFuncSetAttribute(gt2_k, cudaFuncAttributeMaxDynamicSharedMemorySize, GT2_SMEM);
        cudaFuncSetAttribute(fused_main, cudaFuncAttributeMaxDynamicSharedMemorySize, FM_SMEM);
        init_done = true;
    }

    cudaEventRecord(evFork, 0);
    cudaStreamWaitEvent(s2, evFork, 0);
    cudaStreamWaitEvent(s3, evFork, 0);

    // s2: nearest vertex (independent)
    argmin_k<<<NQV / 256, 256, 0, s2>>>(v, vert, idx);
    cudaEventRecord(evJ2, s2);

    // s3: vertex sampling + c3 branch (ft1 64x64)
    feat_vert_k<<<(NVV + 255) / 256, 256, 0, s3>>>(vert_xy, img, ft1, vf);
    conv3x3<8, 21, 64, false><<<dim3(4, 8), 128, 8*180*4 + 8*9*12*8, s3>>>(
        ft1, c3_w1, B21, nullptr, nullptr, nullptr);
    stats_partial<<<dim3(21, NB), 256, 0, s3>>>(B21, 4096, partB);
    conv3x3<21, 42, 64, true><<<dim3(4, 8), 128, 21*180*4 + 21*9*22*8, s3>>>(
        B21, c3_w2, B42, partB, c3_g1, c3_b1);
    stats_partial<<<dim3(42, NB), 256, 0, s3>>>(B42, 4096, partB);
    apool<<<dim3(9, 42), 256, 0, s3>>>(B42, 64, partB, c3_g2, c3_b2, gf, 9);
    cudaEventRecord(evJ3, s3);

    // main: c4 branch (img_fmap 256x256)
    conv3x3<3, 21, 256, false><<<dim3(16, 32), 128, 3*180*4 + 3*9*12*8>>>(
        img, c4_w1, A21, nullptr, nullptr, nullptr);
    stats_partial<<<dim3(21, NB), 256>>>(A21, 65536, partA);
    conv3x3<21, 42, 256, true><<<dim3(16, 32), 128, 21*180*4 + 21*9*22*8>>>(
        A21, c4_w2, A42, partA, c4_g1, c4_b1);
    stats_partial<<<dim3(42, NB), 256>>>(A42, 65536, partA);
    apool<<<dim3(9, 42), 256>>>(A42, 256, partA, c4_g2, c4_b2, gf, 0);

    // join c3 branch, then graph convs
    cudaStreamWaitEvent(0, evJ3, 0);
    gt1_k<<<NUMVV, 32>>>(gf, gt_w1, gt_g1, gt_b1, H779);
    gt2_k<<<(NVV + GT2_OPB - 1) / GT2_OPB, 256, GT2_SMEM>>>(H779, gt_w2, gt_g2, gt_b2, vf);

    // join argmin, then fused MLP (persistent, prefetched gather)
    cudaStreamWaitEvent(0, evJ2, 0);
    fused_main<<<FM_GRID, 512, FM_SMEM>>>(img_xy, ft_xy, latent, qvis, vvis,
                                          at_w1, at_w2, fw1, fw2, out);
}

// round 15
// speedup vs baseline: 1.0868x; 1.0003x over previous
#include <cuda_runtime.h>
#include <math.h>

#define NQV   65536
#define NVV   1558
#define NUMVV 779
#define NB    32

typedef unsigned long long ull;

__device__ __forceinline__ ull pack2(float lo, float hi) {
    ull r; asm("mov.b64 %0,{%1,%2};" : "=l"(r) : "f"(lo), "f"(hi)); return r;
}
__device__ __forceinline__ float2 unpk(ull v) {
    float2 r; asm("mov.b64 {%0,%1},%2;" : "=f"(r.x), "=f"(r.y) : "l"(v)); return r;
}
__device__ __forceinline__ ull ffma2(ull a, ull b, ull c) {
    ull d; asm("fma.rn.f32x2 %0,%1,%2,%3;" : "=l"(d) : "l"(a), "l"(b), "l"(c)); return d;
}
__device__ __forceinline__ ull fadd2(ull a, ull b) {
    ull d; asm("add.rn.f32x2 %0,%1,%2;" : "=l"(d) : "l"(a), "l"(b)); return d;
}
__device__ __forceinline__ ull fmul2(ull a, ull b) {
    ull d; asm("mul.rn.f32x2 %0,%1,%2;" : "=l"(d) : "l"(a), "l"(b)); return d;
}

// scratch
__device__ float  g_A21[21*256*256];
__device__ float  g_A42[42*256*256];
__device__ float  g_B21[21*64*64];
__device__ float  g_B42[42*64*64];
__device__ float2 g_partA[42*NB];
__device__ float2 g_partB[42*NB];
__device__ float  g_gf[42*18];
__device__ float  g_H779[NUMVV*18];
__device__ float  g_vf[NVV*29];
__device__ int    g_idx[NQV];

// ---------------- 2-level channel stats: partial sums ----------------
__global__ void stats_partial(const float* __restrict__ x, int N, float2* __restrict__ part)
{
    __shared__ float s1[256], s2[256];
    int c = blockIdx.x, b = blockIdx.y;
    int cnt = N / 4 / NB;
    const float4* p = (const float4*)(x + (size_t)c * N) + (size_t)b * cnt;
    float a = 0.f, q = 0.f;
    for (int i = threadIdx.x; i < cnt; i += 256) {
        float4 v = p[i];
        a += v.x + v.y + v.z + v.w;
        q += v.x*v.x + v.y*v.y + v.z*v.z + v.w*v.w;
    }
    s1[threadIdx.x] = a; s2[threadIdx.x] = q;
    __syncthreads();
    for (int s = 128; s > 0; s >>= 1) {
        if (threadIdx.x < s) { s1[threadIdx.x] += s1[threadIdx.x+s]; s2[threadIdx.x] += s2[threadIdx.x+s]; }
        __syncthreads();
    }
    if (threadIdx.x == 0) part[c * NB + b] = make_float2(s1[0], s2[0]);
}

__device__ __forceinline__ float2 fold_stats(const float2* __restrict__ part, int c, float invN)
{
    float a = 0.f, q = 0.f;
#pragma unroll
    for (int i = 0; i < NB; i++) { float2 p = part[c * NB + i]; a += p.x; q += p.y; }
    float m = a * invN;
    return make_float2(m, rsqrtf(q * invN - m * m + 1e-6f));
}

// ---------------- 3x3 conv pad1, f32x2 channel pairs ----------------
// ZS-way output-channel split across blockIdx.z (each CTA computes PC pairs).
template<int CIN, int COUT, int HW, bool FLN, int ZS>
__global__ __launch_bounds__(128) void conv3x3(const float* __restrict__ in,
                                               const float* __restrict__ w,
                                               float* __restrict__ out,
                                               const float2* __restrict__ part,
                                               const float* __restrict__ lng,
                                               const float* __restrict__ lnb)
{
    constexpr int NP  = (COUT + 1) / 2;          // total channel pairs
    constexpr int PC  = (NP + ZS - 1) / ZS;      // pairs per CTA
    constexpr int PCP = (PC + 1) & ~1;           // padded even
    extern __shared__ float sm[];
    float* sin_ = sm;                            // CIN*10*18 halo tile
    ull*   swt  = (ull*)(sm + CIN * 180);        // [CIN*9][PCP] packed channel pairs
    __shared__ float sMean[32], sRstd[32];
    int tid = threadIdx.x;
    int bx = blockIdx.x * 16, by = blockIdx.y * 8;
    int zb = blockIdx.z * PC;                    // first pair handled by this CTA

    if (FLN && tid < CIN) {
        float2 mr = fold_stats(part, tid, 1.f / (float)(HW * HW));
        sMean[tid] = mr.x; sRstd[tid] = mr.y;
    }
    if (FLN) __syncthreads();

    for (int i = tid; i < CIN * 180; i += 128) {
        int ci = i / 180, r = (i % 180) / 18, c = i % 18;
        int gy = by + r - 1, gx = bx + c - 1;
        float v = 0.f;
        if (gy >= 0 && gy < HW && gx >= 0 && gx < HW) {
            v = in[ci * HW * HW + gy * HW + gx];
            if (FLN) {
                int pix = gy * HW + gx;
                v = fmaxf((v - sMean[ci]) * sRstd[ci] * lng[pix] + lnb[pix], 0.f);
            }
        }
        sin_[i] = v;
    }
    for (int i = tid; i < CIN * 9 * PCP; i += 128) {
        int kk = i / PCP, p = i % PCP;
        int gp = zb + p;
        float lo = (p < PC && 2*gp   < COUT) ? w[(2*gp)   * CIN * 9 + kk] : 0.f;
        float hi = (p < PC && 2*gp+1 < COUT) ? w[(2*gp+1) * CIN * 9 + kk] : 0.f;
        swt[i] = pack2(lo, hi);
    }
    __syncthreads();

    int px = tid & 15, py = tid >> 4;
    ull acc[PCP];
#pragma unroll
    for (int p = 0; p < PCP; p++) acc[p] = 0ull;

    for (int ci = 0; ci < CIN; ci++) {
#pragma unroll
        for (int ky = 0; ky < 3; ky++)
#pragma unroll
        for (int kx = 0; kx < 3; kx++) {
            float v = sin_[ci * 180 + (py + ky) * 18 + px + kx];
            ull vd = pack2(v, v);
            const ull* wr = swt + (ci * 9 + ky * 3 + kx) * PCP;
#pragma unroll
            for (int p = 0; p < PCP; p += 2) {
                ulonglong2 wp = *(const ulonglong2*)(wr + p);
                acc[p]   = ffma2(vd, wp.x, acc[p]);
                acc[p+1] = ffma2(vd, wp.y, acc[p+1]);
            }
        }
    }
    int ox = bx + px, oy = by + py;
#pragma unroll
    for (int p = 0; p < PC; p++) {
        int gp = zb + p;
        if (gp >= NP) break;
        float2 r = unpk(acc[p]);
        out[(2*gp) * HW * HW + oy * HW + ox] = r.x;
        if (2*gp+1 < COUT) out[(2*gp+1) * HW * HW + oy * HW + ox] = r.y;
    }
}

// ---------------- adaptive avg pool -> 3x3 with fused LN+relu (stats folded) ----------------
__global__ void apool(const float* __restrict__ A, int HW,
                      const float2* __restrict__ part,
                      const float* __restrict__ lng,  const float* __restrict__ lnb,
                      float* __restrict__ gf, int colbase)
{
    __shared__ float sred[256];
    __shared__ float sM, sR;
    int r = blockIdx.x, c = blockIdx.y;
    if (threadIdx.x == 0) {
        float2 mr = fold_stats(part, c, 1.f / (float)(HW * HW));
        sM = mr.x; sR = mr.y;
    }
    __syncthreads();
    int ri = r / 3, rj = r % 3;
    int ylo = ri * HW / 3, yhi = ((ri + 1) * HW + 2) / 3;
    int xlo = rj * HW / 3, xhi = ((rj + 1) * HW + 2) / 3;
    int wl = xhi - xlo, cnt = (yhi - ylo) * wl;
    const float* base = A + (size_t)c * HW * HW;
    float m = sM, rs = sR;
    float s = 0.f;
    for (int i = threadIdx.x; i < cnt; i += 256) {
        int y = ylo + i / wl, x = xlo + i % wl;
        int pix = y * HW + x;
        s += fmaxf((base[pix] - m) * rs * lng[pix] + lnb[pix], 0.f);
    }
    sred[threadIdx.x] = s;
    __syncthreads();
    for (int st = 128; st > 0; st >>= 1) {
        if (threadIdx.x < st) sred[threadIdx.x] += sred[threadIdx.x + st];
        __syncthreads();
    }
    if (threadIdx.x == 0) gf[c * 18 + colbase + r] = sred[0] / (float)cnt;
}

__device__ __forceinline__ float wsum(float v)
{
#pragma unroll
    for (int o = 16; o > 0; o >>= 1) v += __shfl_xor_sync(0xffffffffu, v, o);
    return v;
}

// ---------------- gt1: conv1d3 42->779 len18, LN(18)+relu ----------------
__global__ void gt1_k(const float* __restrict__ gf, const float* __restrict__ w,
                      const float* __restrict__ g, const float* __restrict__ b,
                      float* __restrict__ out)
{
    __shared__ float s[42 * 18];
    int o = blockIdx.x, t = threadIdx.x;
    for (int i = t; i < 42 * 18; i += 32) s[i] = gf[i];
    __syncthreads();
    float acc = 0.f;
    if (t < 18) {
        const float* wo = w + o * 126;
        for (int c = 0; c < 42; c++) {
#pragma unroll
            for (int k = 0; k < 3; k++) {
                int tt = t + k - 1;
                if (tt >= 0 && tt < 18) acc = fmaf(s[c * 18 + tt], wo[c * 3 + k], acc);
            }
        }
    }
    float v  = (t < 18) ? acc : 0.f;
    float m  = wsum(v) / 18.f;
    float sq = wsum(v * v) / 18.f;
    float rs = rsqrtf(sq - m * m + 1e-6f);
    if (t < 18) out[o * 18 + t] = fmaxf((acc - m) * rs * g[t] + b[t], 0.f);
}

// ---------------- gt2: conv1d3 779->1558 len18, LN(18)+relu -> vf[:,11:29] ----------------
// H rows stored padded as 20 floats: [0, h0..h17, 0] -> aligned ull pairs, f32x2 inner loop.
#define GT2_OPB 16
#define GT2_SMEM ((779*20 + GT2_OPB*2337) * 4)
__global__ __launch_bounds__(256) void gt2_k(const float* __restrict__ h,
                                             const float* __restrict__ w,
                                             const float* __restrict__ g,
                                             const float* __restrict__ b,
                                             float* __restrict__ vf)
{
    extern __shared__ float sm[];
    float* Hs = sm;               // 779 x 20 padded [0, h0..h17, 0]
    float* Ws = sm + 779 * 20;    // GT2_OPB x 2337
    int ob  = blockIdx.x * GT2_OPB;
    int tid = threadIdx.x;
    int nout = NVV - ob; if (nout > GT2_OPB) nout = GT2_OPB;

    for (int i = tid; i < 779 * 18; i += 256) Hs[(i / 18) * 20 + 1 + (i % 18)] = h[i];
    for (int i = tid; i < 779; i += 256) { Hs[i * 20] = 0.f; Hs[i * 20 + 19] = 0.f; }
    for (int i = tid; i < nout * 2337; i += 256) Ws[i] = w[(size_t)ob * 2337 + i];
    __syncthreads();

    int wid = tid >> 5, lane = tid & 31;
#pragma unroll
    for (int rep = 0; rep < 2; rep++) {
        int oo = wid + rep * 8;
        if (oo >= nout) continue;
        int o = ob + oo;
        ull acc[9];
#pragma unroll
        for (int j = 0; j < 9; j++) acc[j] = 0ull;
        for (int c = lane; c < NUMVV; c += 32) {
            const float* wc = Ws + oo * 2337 + c * 3;
            ull w0 = pack2(wc[0], wc[0]);
            ull w1 = pack2(wc[1], wc[1]);
            ull w2 = pack2(wc[2], wc[2]);
            const ull* U = (const ull*)(Hs + c * 20);
            ull u[10];
#pragma unroll
            for (int j = 0; j < 10; j++) u[j] = U[j];
#pragma unroll
            for (int j = 0; j < 9; j++) {
                float2 a = unpk(u[j]);
                float2 bb = unpk(u[j + 1]);
                ull mid = pack2(a.y, bb.x);
                acc[j] = ffma2(w0, u[j], acc[j]);
                acc[j] = ffma2(w1, mid, acc[j]);
                acc[j] = ffma2(w2, u[j + 1], acc[j]);
            }
        }
        float av[18];
#pragma unroll
        for (int j = 0; j < 9; j++) {
            float2 r = unpk(acc[j]);
            av[2*j] = r.x; av[2*j + 1] = r.y;
        }
#pragma unroll
        for (int t = 0; t < 18; t++) av[t] = wsum(av[t]);
        float m = 0.f, sq = 0.f;
#pragma unroll
        for (int t = 0; t < 18; t++) { m += av[t]; sq += av[t] * av[t]; }
        m *= (1.f / 18.f); sq *= (1.f / 18.f);
        float rs = rsqrtf(sq - m * m + 1e-6f);
        if (lane < 18)
            vf[o * 29 + 11 + lane] = fmaxf((av[lane] - m) * rs * g[lane] + b[lane], 0.f);
    }
}

// ---------------- bilinear vertex sampling -> vf[:,0:11] ----------------
__device__ __forceinline__ void bsetup(float c, int L, int& i0, int& i1, float& w)
{
    float xs = (c + 1.f) * 0.5f * (float)(L - 1);
    float f = floorf(xs);
    w = xs - f;
    int a = (int)f;
    i0 = min(max(a, 0), L - 1);
    i1 = min(max(a + 1, 0), L - 1);
}

__global__ void feat_vert_k(const float* __restrict__ vxy, const float* __restrict__ img,
                            const float* __restrict__ ft, float* __restrict__ vf)
{
    int p = blockIdx.x * 256 + threadIdx.x;
    if (p >= NVV) return;
    float xc = vxy[p * 2], yc = vxy[p * 2 + 1];
    int x0, x1, y0, y1; float wx, wy;
    bsetup(xc, 256, x0, x1, wx); bsetup(yc, 256, y0, y1, wy);
#pragma unroll
    for (int c = 0; c < 3; c++) {
        const float* f = img + c * 65536;
        float v00=f[y0*256+x0], v01=f[y0*256+x1], v10=f[y1*256+x0], v11=f[y1*256+x1];
        vf[p*29+c] = v00*(1.f-wx)*(1.f-wy) + v01*wx*(1.f-wy) + v10*(1.f-wx)*wy + v11*wx*wy;
    }
    bsetup(xc, 64, x0, x1, wx); bsetup(yc, 64, y0, y1, wy);
#pragma unroll
    for (int c = 0; c < 8; c++) {
        const float* f = ft + c * 4096;
        float v00=f[y0*64+x0], v01=f[y0*64+x1], v10=f[y1*64+x0], v11=f[y1*64+x1];
        vf[p*29+3+c] = v00*(1.f-wx)*(1.f-wy) + v01*wx*(1.f-wy) + v10*(1.f-wx)*wy + v11*wx*wy;
    }
}

// ---------------- nearest-vertex argmin, f32x2 pairs (1 query/thread) ----------------
__global__ __launch_bounds__(256) void argmin_k(const float* __restrict__ v,
                                                const float* __restrict__ vert,
                                                int* __restrict__ idx)
{
    __shared__ __align__(16) float sx[NVV];
    __shared__ __align__(16) float sy[NVV];
    __shared__ __align__(16) float sz[NVV];
    __shared__ __align__(16) float s2[NVV];
    int tid = threadIdx.x;
    for (int i = tid; i < NVV; i += 256) {
        float x = vert[i*3], y = vert[i*3+1], z = vert[i*3+2];
        sx[i] = x; sy[i] = y; sz[i] = z; s2[i] = x*x + y*y + z*z;
    }
    __syncthreads();
    int q = blockIdx.x * 256 + tid;
    float qx = v[q*3], qy = v[q*3+1], qz = v[q*3+2];
    ull qx2 = pack2(qx, qx), qy2 = pack2(qy, qy), qz2 = pack2(qz, qz);
    ull m2  = pack2(-2.f, -2.f);
    float best = 3.4e38f; int bi = 0;
    for (int p = 0; p < NVV; p += 2) {
        ull x2 = *(const ull*)(sx + p);
        ull y2 = *(const ull*)(sy + p);
        ull z2 = *(const ull*)(sz + p);
        ull s22 = *(const ull*)(s2 + p);
        ull dot = ffma2(x2, qx2, ffma2(y2, qy2, fmul2(z2, qz2)));
        ull d2  = ffma2(dot, m2, s22);
        float2 dd = unpk(d2);
        if (dd.x < best) { best = dd.x; bi = p; }
        if (dd.y < best) { best = dd.y; bi = p + 1; }
    }
    idx[q] = bi;
}

// ---------------- fused per-query MLP stack (persistent CTAs, prefetched gather) ----------------
#define QT 128
#define NTILE (NQV / QT)   // 512
#define FM_GRID 148
#define FM_SMEM 196864

__device__ __forceinline__ void gather24(int qb, int tid,
    const float* __restrict__ img_xy, const float* __restrict__ ft_xy,
    const float* __restrict__ latent, const float* __restrict__ qvis,
    const float* __restrict__ vvis, float* pf)
{
#pragma unroll
    for (int i = 0; i < 24; i++) {
        int e = tid + i * 512;
        int q = e / 96, c = e % 96, gq = qb + q;
        float val;
        if (c < 3) val = img_xy[gq * 3 + c];
        else if (c < 11) val = ft_xy[gq * 8 + (c - 3)];
        else if (c < 69) {
            int i0 = g_idx[gq];
            int i1 = i0 + NUMVV; if (i1 >= NVV) i1 -= NVV;
            if (c < 22)      val = g_vf[i0 * 29 + (c - 11)]      * vvis[i0];
            else if (c < 33) val = g_vf[i1 * 29 + (c - 22)]      * vvis[i1];
            else if (c < 51) val = g_vf[i0 * 29 + 11 + (c - 33)] * vvis[i0];
            else             val = g_vf[i1 * 29 + 11 + (c - 51)] * vvis[i1];
        }
        else if (c < 93) val = latent[gq * 24 + (c - 69)];
        else if (c == 93) val = qvis[gq];
        else {
            int i0 = g_idx[gq];
            if (c == 94) val = vvis[i0];
            else { int i1 = i0 + NUMVV; if (i1 >= NVV) i1 -= NVV; val = vvis[i1]; }
        }
        pf[i] = val;
    }
}

__device__ __forceinline__ void gemm_relu2(const float* __restrict__ A,
                                           const ull* __restrict__ WT,
                                           float* __restrict__ C, int tid)
{
    int q0 = (tid >> 4) << 2;
    int t16 = tid & 15;
    ull acc[4][3];
#pragma unroll
    for (int i = 0; i < 4; i++)
#pragma unroll
        for (int j = 0; j < 3; j++) acc[i][j] = 0ull;
#pragma unroll 2
    for (int ks = 0; ks < 96; ks += 4) {
        float4 a4[4];
#pragma unroll
        for (int i = 0; i < 4; i++) a4[i] = *(const float4*)(A + (q0 + i) * 100 + ks);
        ull w[4][3];
#pragma unroll
        for (int k = 0; k < 4; k++)
#pragma unroll
            for (int j = 0; j < 3; j++)
                w[k][j] = WT[(ks + k) * 48 + t16 + 16 * j];
#pragma unroll
        for (int i = 0; i < 4; i++) {
            ull ak[4];
            ak[0] = pack2(a4[i].x, a4[i].x); ak[1] = pack2(a4[i].y, a4[i].y);
            ak[2] = pack2(a4[i].z, a4[i].z); ak[3] = pack2(a4[i].w, a4[i].w);
#pragma unroll
            for (int k = 0; k < 4; k++)
#pragma unroll
                for (int j = 0; j < 3; j++)
                    acc[i][j] = ffma2(ak[k], w[k][j], acc[i][j]);
        }
    }
#pragma unroll
    for (int i = 0; i < 4; i++)
#pragma unroll
        for (int j = 0; j < 3; j++) {
            float2 r = unpk(acc[i][j]);
            float2 o;
            o.x = fmaxf(r.x, 0.f);
            o.y = fmaxf(r.y, 0.f);
            *(float2*)(C + (q0 + i) * 100 + 2 * (t16 + 16 * j)) = o;
        }
}

__global__ __launch_bounds__(512) void fused_main(
    const float* __restrict__ img_xy, const float* __restrict__ ft_xy,
    const float* __restrict__ latent, const float* __restrict__ qvis,
    const float* __restrict__ vvis,
    const float* __restrict__ at_w1, const float* __restrict__ at_w2,
    const float* __restrict__ fw1, const float* __restrict__ fw2,
    float* __restrict__ out)
{
    extern __shared__ char smc[];
    ull*   uW1 = (ull*)smc;                 // [96][48] k-major pairs of at_w1
    ull*   uF1 = uW1 + 4608;                // [96][48] k-major pairs of fconv_w1
    ull*   uW2 = uF1 + 4608;                // [96][3]  k-major o-pairs of at_w2
    ull*   uF2 = uW2 + 288;                 // [96][20] k-major o-pairs of fconv_w2
    float* Ys  = (float*)(uF2 + 1920);      // 128 x 100
    float* Hs  = Ys + 12800;                // 128 x 100
    float* ATs = Hs + 12800;                // 128 x 6
    int tid = threadIdx.x;

    for (int i = tid; i < 48 * 96; i += 512) {
        int k = i / 48, p = i % 48;
        uW1[i] = pack2(at_w1[(2*p) * 96 + k], at_w1[(2*p+1) * 96 + k]);
        uF1[i] = pack2(fw1[(2*p) * 96 + k],   fw1[(2*p+1) * 96 + k]);
    }
    for (int i = tid; i < 3 * 96; i += 512) {
        int p = i / 96, k = i % 96;
        uW2[k * 3 + p] = pack2(at_w2[(2*p) * 96 + k], at_w2[(2*p+1) * 96 + k]);
    }
    for (int i = tid; i < 20 * 96; i += 512) {
        int p = i / 96, k = i % 96;
        uF2[k * 20 + p] = pack2(fw2[(2*p) * 96 + k], fw2[(2*p+1) * 96 + k]);
    }

    float pf[24];
    int t0 = blockIdx.x;
    if (t0 < NTILE) gather24(t0 * QT, tid, img_xy, ft_xy, latent, qvis, vvis, pf);

    for (int t = t0; t < NTILE; t += FM_GRID) {
        int qb = t * QT;
#pragma unroll
        for (int i = 0; i < 24; i++) {
            int e = tid + i * 512;
            Ys[(e / 96) * 100 + (e % 96)] = pf[i];
        }
        __syncthreads();

        int tn = t + FM_GRID;
        if (tn < NTILE) gather24(tn * QT, tid, img_xy, ft_xy, latent, qvis, vvis, pf);

        gemm_relu2(Ys, uW1, Hs, tid);           // h1 = relu(at_w1 @ y)
        __syncthreads();

        for (int e = tid; e < QT * 3; e += 512) {   // at = sigmoid(at_w2 @ h1)
            int q = e / 3, p = e % 3;
            ull acc0 = 0ull, acc1 = 0ull;
#pragma unroll 6
            for (int k = 0; k < 96; k += 4) {
                float4 h = *(const float4*)(Hs + q * 100 + k);
                acc0 = ffma2(pack2(h.x, h.x), uW2[(k  ) * 3 + p], acc0);
                acc1 = ffma2(pack2(h.y, h.y), uW2[(k+1) * 3 + p], acc1);
                acc0 = ffma2(pack2(h.z, h.z), uW2[(k+2) * 3 + p], acc0);
                acc1 = ffma2(pack2(h.w, h.w), uW2[(k+3) * 3 + p], acc1);
            }
            float2 r = unpk(fadd2(acc0, acc1));
            ATs[q * 6 + 2*p]     = 1.f / (1.f + expf(-r.x));
            ATs[q * 6 + 2*p + 1] = 1.f / (1.f + expf(-r.y));
        }
        __syncthreads();

        for (int e = tid; e < QT * 96; e += 512) {  // y2: scale sections
            int q = e / 96, c = e % 96;
            int s = (c < 11) ? 0 : (c < 22) ? 1 : (c < 33) ? 2 : (c < 51) ? 3 : (c < 69) ? 4 : (c < 93) ? 5 : -1;
            if (s >= 0) Ys[q * 100 + c] *= ATs[q * 6 + s];
        }
        __syncthreads();

        gemm_relu2(Ys, uF1, Hs, tid);           // h2 = relu(fconv_w1 @ y2)
        __syncthreads();

        if (tid < 256) {                        // out = fconv_w2 @ h2
            int q = tid >> 1, pg = tid & 1;
            const ull* wb = uF2 + pg * 10;
            const float* hq = Hs + q * 100;
            ull acc[10];
#pragma unroll
            for (int j = 0; j < 10; j++) acc[j] = 0ull;
#pragma unroll 4
            for (int k = 0; k < 96; k += 2) {
                float2 a = *(const float2*)(hq + k);
                ull ax = pack2(a.x, a.x), ay = pack2(a.y, a.y);
                const ulonglong2* w0 = (const ulonglong2*)(wb + (k    ) * 20);
                const ulonglong2* w1 = (const ulonglong2*)(wb + (k + 1) * 20);
#pragma unroll
                for (int j = 0; j < 5; j++) {
                    ulonglong2 wa = w0[j], wc = w1[j];
                    acc[2*j]   = ffma2(ax, wa.x, acc[2*j]);
                    acc[2*j]   = ffma2(ay, wc.x, acc[2*j]);
                    acc[2*j+1] = ffma2(ax, wa.y, acc[2*j+1]);
                    acc[2*j+1] = ffma2(ay, wc.y, acc[2*j+1]);
                }
            }
            float* ob = out + (size_t)(qb + q) * 40 + pg * 20;
#pragma unroll
            for (int j = 0; j < 5; j++) {
                float2 r0 = unpk(acc[2*j]), r1 = unpk(acc[2*j+1]);
                float4 o4 = make_float4(r0.x, r0.y, r1.x, r1.y);
                *(float4*)(ob + 4*j) = o4;
            }
        }
        __syncthreads();
    }
}

extern "C" void kernel_launch(void* const* d_in, const int* in_sizes, int n_in,
                              void* d_out, int out_size)
{
    const float* vert_xy = (const float*)d_in[0];
    const float* ft1     = (const float*)d_in[1];
    const float* ft_xy   = (const float*)d_in[2];
    const float* vert    = (const float*)d_in[3];
    const float* v       = (const float*)d_in[4];
    const float* vvis    = (const float*)d_in[5];
    const float* qvis    = (const float*)d_in[6];
    const float* img_xy  = (const float*)d_in[7];
    const float* img     = (const float*)d_in[8];
    const float* latent  = (const float*)d_in[9];
    const float* fw1     = (const float*)d_in[10];
    const float* fw2     = (const float*)d_in[11];
    const float* at_w1   = (const float*)d_in[12];
    const float* at_w2   = (const float*)d_in[13];
    const float* gt_w1   = (const float*)d_in[14];
    const float* gt_g1   = (const float*)d_in[15];
    const float* gt_b1   = (const float*)d_in[16];
    const float* gt_w2   = (const float*)d_in[17];
    const float* gt_g2   = (const float*)d_in[18];
    const float* gt_b2   = (const float*)d_in[19];
    const float* c3_w1   = (const float*)d_in[20];
    const float* c3_g1   = (const float*)d_in[21];
    const float* c3_b1   = (const float*)d_in[22];
    const float* c3_w2   = (const float*)d_in[23];
    const float* c3_g2   = (const float*)d_in[24];
    const float* c3_b2   = (const float*)d_in[25];
    const float* c4_w1   = (const float*)d_in[26];
    const float* c4_g1   = (const float*)d_in[27];
    const float* c4_b1   = (const float*)d_in[28];
    const float* c4_w2   = (const float*)d_in[29];
    const float* c4_g2   = (const float*)d_in[30];
    const float* c4_b2   = (const float*)d_in[31];
    float* out = (float*)d_out;

    float *A21, *A42, *B21, *B42, *gf, *H779, *vf;
    float2 *partA, *partB;
    int* idx;
    cudaGetSymbolAddress((void**)&A21,   g_A21);
    cudaGetSymbolAddress((void**)&A42,   g_A42);
    cudaGetSymbolAddress((void**)&B21,   g_B21);
    cudaGetSymbolAddress((void**)&B42,   g_B42);
    cudaGetSymbolAddress((void**)&partA, g_partA);
    cudaGetSymbolAddress((void**)&partB, g_partB);
    cudaGetSymbolAddress((void**)&gf,    g_gf);
    cudaGetSymbolAddress((void**)&H779,  g_H779);
    cudaGetSymbolAddress((void**)&vf,    g_vf);
    cudaGetSymbolAddress((void**)&idx,   g_idx);

    static bool init_done = false;
    static cudaStream_t s2, s3;
    static cudaEvent_t evFork, evJ2, evJ3;
    if (!init_done) {
        cudaStreamCreateWithFlags(&s2, cudaStreamNonBlocking);
        cudaStreamCreateWithFlags(&s3, cudaStreamNonBlocking);
        cudaEventCreateWithFlags(&evFork, cudaEventDisableTiming);
        cudaEventCreateWithFlags(&evJ2, cudaEventDisableTiming);
        cudaEventCreateWithFlags(&evJ3, cudaEventDisableTiming);
        cudaFuncSetAttribute(gt2_k, cudaFuncAttributeMaxDynamicSharedMemorySize, GT2_SMEM);
        cudaFuncSetAttribute(fused_main, cudaFuncAttributeMaxDynamicSharedMemorySize, FM_SMEM);
        init_done = true;
    }

    cudaEventRecord(evFork, 0);
    cudaStreamWaitEvent(s2, evFork, 0);
    cudaStreamWaitEvent(s3, evFork, 0);

    // s2: nearest vertex (independent)
    argmin_k<<<NQV / 256, 256, 0, s2>>>(v, vert, idx);
    cudaEventRecord(evJ2, s2);

    // s3: vertex sampling + c3 branch (ft1 64x64); conv2 split 4-way over channels
    feat_vert_k<<<(NVV + 255) / 256, 256, 0, s3>>>(vert_xy, img, ft1, vf);
    conv3x3<8, 21, 64, false, 1><<<dim3(4, 8), 128, 8*180*4 + 8*9*12*8, s3>>>(
        ft1, c3_w1, B21, nullptr, nullptr, nullptr);
    stats_partial<<<dim3(21, NB), 256, 0, s3>>>(B21, 4096, partB);
    conv3x3<21, 42, 64, true, 4><<<dim3(4, 8, 4), 128, 21*180*4 + 21*9*6*8, s3>>>(
        B21, c3_w2, B42, partB, c3_g1, c3_b1);
    stats_partial<<<dim3(42, NB), 256, 0, s3>>>(B42, 4096, partB);
    apool<<<dim3(9, 42), 256, 0, s3>>>(B42, 64, partB, c3_g2, c3_b2, gf, 9);
    cudaEventRecord(evJ3, s3);

    // main: c4 branch (img_fmap 256x256)
    conv3x3<3, 21, 256, false, 1><<<dim3(16, 32), 128, 3*180*4 + 3*9*12*8>>>(
        img, c4_w1, A21, nullptr, nullptr, nullptr);
    stats_partial<<<dim3(21, NB), 256>>>(A21, 65536, partA);
    conv3x3<21, 42, 256, true, 1><<<dim3(16, 32), 128, 21*180*4 + 21*9*22*8>>>(
        A21, c4_w2, A42, partA, c4_g1, c4_b1);
    stats_partial<<<dim3(42, NB), 256>>>(A42, 65536, partA);
    apool<<<dim3(9, 42), 256>>>(A42, 256, partA, c4_g2, c4_b2, gf, 0);

    // join c3 branch, then graph convs
    cudaStreamWaitEvent(0, evJ3, 0);
    gt1_k<<<NUMVV, 32>>>(gf, gt_w1, gt_g1, gt_b1, H779);
    gt2_k<<<(NVV + GT2_OPB - 1) / GT2_OPB, 256, GT2_SMEM>>>(H779, gt_w2, gt_g2, gt_b2, vf);

    // join argmin, then fused MLP (persistent, prefetched gather)
    cudaStreamWaitEvent(0, evJ2, 0);
    fused_main<<<FM_GRID, 512, FM_SMEM>>>(img_xy, ft_xy, latent, qvis, vvis,
                                          at_w1, at_w2, fw1, fw2, out);
}